// round 16
// baseline (speedup 1.0000x reference)
#include <cuda_runtime.h>
#include <cuda_bf16.h>
#include <math.h>

// Problem dims (fixed by the reference)
#define NT    16384          // N*T rows
#define WDIM  512            // feature dim
#define KC    2048           // codebook size
#define NB    16             // N
#define TB    1024           // T

#define MU_F   0.99f
#define OMM_F  ((float)(1.0 - 0.99))   // exact JAX constant
#define EPSM   0.125f                  // candidate margin >> bf16 dist error (~0.02 worst)
#define BSLACK 0.03125f                // extra slack for bf16-stored dist rounding
#define MAXB   64                      // max bucket occupancy (Poisson(8); P(>64) ~ 0)

// Output layout (tuple flattened, float32)
#define O_XL     0
#define O_XD     16384
#define O_SCAL   8404992
#define O_KNEW   8404997
#define O_KSUM   9453573
#define O_KELEM  10502149

// -------- scratch (static device globals) --------
__device__ float  g_xf[(size_t)NT * WDIM];
__device__ unsigned int g_xfh[(size_t)NT * (WDIM / 2)];  // bf16x2 copy of xf
__device__ unsigned int g_kh[(size_t)KC * (WDIM / 2)];   // bf16x2 copy of k
__device__ float  g_rownorm[NT];
__device__ float  g_knorm[KC];
__device__ int    g_xl[NT];
__device__ unsigned long long g_best[NT];        // approx (monotone distbits)<<32 | idx
__device__ unsigned int g_distb[(size_t)NT * (KC / 2)];  // 64 MiB bf16x2 approx dist
__device__ float  g_ksum_acc[(size_t)KC * WDIM];
__device__ float  g_kelem_acc[KC];
__device__ double g_red[8];                      // 0 sum, 1 sumsq, 2 fit, 3 commit, 4 dk
// permutation machinery (jax.random.permutation(key(42), xf) reproduction)
__device__ unsigned int g_sk[2][NT];
__device__ int    g_cnt[2][2048];                // bucket counts
__device__ int    g_basep[2][2048];              // bucket exclusive prefix
__device__ int    g_mem[2][2048 * MAXB];         // bucket member lists
__device__ int    g_v1[NT];
__device__ int    g_ind[NT];

// -------- helpers --------
__device__ __forceinline__ float warp_sum(float v) {
    #pragma unroll
    for (int o = 16; o > 0; o >>= 1) v += __shfl_xor_sync(0xffffffffu, v, o);
    return v;
}
__device__ __forceinline__ double warp_sum_d(double v) {
    #pragma unroll
    for (int o = 16; o > 0; o >>= 1) v += __shfl_xor_sync(0xffffffffu, v, o);
    return v;
}

// monotone float->uint map (order-preserving for all finite floats)
__device__ __forceinline__ unsigned int fmono(float f) {
    unsigned int b = __float_as_uint(f);
    return (b & 0x80000000u) ? ~b : (b | 0x80000000u);
}
__device__ __forceinline__ float fmono_inv(unsigned int u) {
    unsigned int b = (u & 0x80000000u) ? (u & 0x7FFFFFFFu) : ~u;
    return __uint_as_float(b);
}

// pack two f32 into bf16x2 (lo -> low 16 bits, hi -> high 16 bits), round-to-nearest
__device__ __forceinline__ unsigned int pk_bf16x2(float lo, float hi) {
    unsigned int w;
    asm("cvt.rn.bf16x2.f32 %0, %1, %2;" : "=r"(w) : "f"(hi), "f"(lo));
    return w;
}

// 16-byte async global->shared copy
__device__ __forceinline__ void cp_async16(unsigned int saddr, const void* gptr) {
    asm volatile("cp.async.ca.shared.global [%0], [%1], 16;"
                 :: "r"(saddr), "l"(gptr));
}

// ldmatrix x4 (b16, non-transposed)
__device__ __forceinline__ void ldsm_x4(unsigned int& r0, unsigned int& r1,
                                        unsigned int& r2, unsigned int& r3,
                                        unsigned int saddr) {
    asm volatile("ldmatrix.sync.aligned.m8n8.x4.shared.b16 {%0,%1,%2,%3}, [%4];"
                 : "=r"(r0), "=r"(r1), "=r"(r2), "=r"(r3) : "r"(saddr));
}

// m16n8k16 bf16 mma, D += A*B
__device__ __forceinline__ void mma_bf16(float* d, const unsigned int* a,
                                         unsigned int b0, unsigned int b1) {
    asm volatile(
        "mma.sync.aligned.m16n8k16.row.col.f32.bf16.bf16.f32 "
        "{%0,%1,%2,%3}, {%4,%5,%6,%7}, {%8,%9}, {%0,%1,%2,%3};"
        : "+f"(d[0]), "+f"(d[1]), "+f"(d[2]), "+f"(d[3])
        : "r"(a[0]), "r"(a[1]), "r"(a[2]), "r"(a[3]), "r"(b0), "r"(b1));
}

// -------- Threefry-2x32 (exact JAX cipher) --------
#define TF_ROUND(x0, x1, r) { x0 += x1; x1 = ((x1) << (r)) | ((x1) >> (32 - (r))); x1 ^= x0; }

__device__ __forceinline__ uint2 threefry2x32(unsigned int k0, unsigned int k1,
                                              unsigned int x0, unsigned int x1) {
    unsigned int k2 = k0 ^ k1 ^ 0x1BD11BDAu;
    x0 += k0; x1 += k1;
    TF_ROUND(x0, x1, 13) TF_ROUND(x0, x1, 15) TF_ROUND(x0, x1, 26) TF_ROUND(x0, x1, 6)
    x0 += k1; x1 += k2 + 1u;
    TF_ROUND(x0, x1, 17) TF_ROUND(x0, x1, 29) TF_ROUND(x0, x1, 16) TF_ROUND(x0, x1, 24)
    x0 += k2; x1 += k0 + 2u;
    TF_ROUND(x0, x1, 13) TF_ROUND(x0, x1, 15) TF_ROUND(x0, x1, 26) TF_ROUND(x0, x1, 6)
    x0 += k0; x1 += k1 + 3u;
    TF_ROUND(x0, x1, 17) TF_ROUND(x0, x1, 29) TF_ROUND(x0, x1, 16) TF_ROUND(x0, x1, 24)
    x0 += k1; x1 += k2 + 4u;
    TF_ROUND(x0, x1, 13) TF_ROUND(x0, x1, 15) TF_ROUND(x0, x1, 26) TF_ROUND(x0, x1, 6)
    x0 += k2; x1 += k0 + 5u;
    return make_uint2(x0, x1);
}

// ================= kernel 0: zero scratch + threefry sort keys ==============
__global__ void vq_zero_kernel() {
    int i = blockIdx.x * blockDim.x + threadIdx.x;
    int stride = gridDim.x * blockDim.x;
    for (int idx = i; idx < KC * WDIM; idx += stride) g_ksum_acc[idx] = 0.0f;
    for (int idx = i; idx < KC;        idx += stride) g_kelem_acc[idx] = 0.0f;
    for (int idx = i; idx < NT;        idx += stride) {
        g_rownorm[idx] = 0.0f;
        g_best[idx] = 0xFFFFFFFFFFFFFFFFull;
    }
    if (i < 2048) { g_cnt[0][i] = 0; g_cnt[1][i] = 0; }
    if (i < 8) g_red[i] = 0.0;
    if (i < NT) {
        uint2 k1 = threefry2x32(0u, 42u, 0u, 0u);
        uint2 s1 = threefry2x32(0u, 42u, 0u, 1u);
        uint2 s2 = threefry2x32(k1.x, k1.y, 0u, 1u);
        uint2 r1 = threefry2x32(s1.x, s1.y, 0u, (unsigned)i);
        g_sk[0][i] = r1.x ^ r1.y;
        uint2 r2 = threefry2x32(s2.x, s2.y, 0u, (unsigned)i);
        g_sk[1][i] = r2.x ^ r2.y;
    }
}

// ================= kernel 1: transpose x[N,W,T] -> xf[NT,W] (+bf16) + stats ==
__global__ void vq_transpose_kernel(const float* __restrict__ x) {
    __shared__ float tile[32][33];
    __shared__ float sWs[8], sWq[8];
    const int n  = blockIdx.z;
    const int w0 = blockIdx.y * 32;
    const int t0 = blockIdx.x * 32;
    const int tx = threadIdx.x;   // 32
    const int ty = threadIdx.y;   // 8

    float ls = 0.0f, lq = 0.0f;
    #pragma unroll
    for (int i = 0; i < 4; i++) {
        int wl = ty + i * 8;
        float v = x[((size_t)n * WDIM + (w0 + wl)) * TB + t0 + tx];
        tile[wl][tx] = v;
        ls += v;
        lq += v * v;
    }
    __syncthreads();
    #pragma unroll
    for (int i = 0; i < 4; i++) {
        int tl = ty + i * 8;
        float v = tile[tx][tl];                      // w = w0+tx, t = t0+tl
        const size_t row = (size_t)(n * TB + t0 + tl);
        g_xf[row * WDIM + w0 + tx] = v;
        float vn = __shfl_down_sync(0xffffffffu, v, 1);
        if ((tx & 1) == 0)
            g_xfh[(row * WDIM + w0 + tx) >> 1] = pk_bf16x2(v, vn);
        float s = warp_sum(v * v);
        if (tx == 0) atomicAdd(&g_rownorm[n * TB + t0 + tl], s);
    }
    ls = warp_sum(ls);
    lq = warp_sum(lq);
    if (tx == 0) { sWs[ty] = ls; sWq[ty] = lq; }
    __syncthreads();
    if (tx == 0 && ty == 0) {
        float a = 0.0f, b = 0.0f;
        #pragma unroll
        for (int j = 0; j < 8; j++) { a += sWs[j]; b += sWq[j]; }
        atomicAdd(&g_red[0], (double)a);
        atomicAdd(&g_red[1], (double)b);
    }
}

// ================= kernel 2: codebook row norms + bf16 copy =================
__global__ void vq_knorm_kernel(const float* __restrict__ kmat) {
    const int lane = threadIdx.x & 31;
    const int warp = threadIdx.x >> 5;
    const int c = blockIdx.x * 4 + warp;
    if (c >= KC) return;
    float s = 0.0f;
    for (int w = lane; w < WDIM; w += 32) {
        float v = kmat[(size_t)c * WDIM + w];
        s += v * v;
        float vn = __shfl_down_sync(0xffffffffu, v, 1);
        if ((lane & 1) == 0)
            g_kh[((size_t)c * WDIM + w) >> 1] = pk_bf16x2(v, vn);
    }
    s = warp_sum(s);
    if (lane == 0) g_knorm[c] = s;
}

// ================= kernel 3a: bf16 tensor-core dist GEMM ====================
// 16x64 warp tile, 64x128 block tile, 3 blocks/SM (<=85 regs) for occupancy.
// 4-stage cp.async pipeline, one barrier per K-step, ldmatrix frag loads.
// Per-(row,code) K accumulation order unchanged -> dist bits identical.
#define ASTRIDE_W 12
#define A_BUFW (64 * ASTRIDE_W)
#define B_BUFW (128 * ASTRIDE_W)

__global__ void __launch_bounds__(256, 3) vq_dist_kernel() {
    __shared__ unsigned int As[4 * A_BUFW];   // 12 KiB
    __shared__ unsigned int Bs[4 * B_BUFW];   // 24 KiB

    const int tid  = threadIdx.x;
    const int lane = tid & 31;
    const int wid  = tid >> 5;
    const int warp_m = wid & 3;          // m offset 16*warp_m
    const int warp_n = wid >> 2;         // n offset 64*warp_n
    const int g   = lane >> 2;
    const int tig = lane & 3;
    const int rBase  = blockIdx.x * 64;
    const int cBase0 = blockIdx.y * 1024;

    // staging: all threads stage B (128 rows x 2 halves); lower half stages A
    const int rb  = tid >> 1;
    const int bkw = (tid & 1) * 4;
    const int ra  = (tid & 127) >> 1;
    const int akw = (tid & 1) * 4;
    const bool doA = (tid < 128);
    const unsigned int* Asrc  = g_xfh + (size_t)(rBase + ra) * (WDIM / 2) + akw;
    const unsigned int* Bsrc0 = g_kh + (size_t)(cBase0 + rb) * (WDIM / 2) + bkw;

    const unsigned int sA0 = (unsigned int)__cvta_generic_to_shared(As);
    const unsigned int sB0 = (unsigned int)__cvta_generic_to_shared(Bs);
    const unsigned int aSt = sA0 + (ra * ASTRIDE_W + akw) * 4;
    const unsigned int bSt = sB0 + (rb * ASTRIDE_W + bkw) * 4;

    // ldmatrix lane offsets (bytes)
    const int am0 = warp_m * 16;
    const int aoff = ((lane < 16) ? (am0 + lane) * ASTRIDE_W
                                  : (am0 + lane - 16) * ASTRIDE_W + 4) * 4;
    int bl;
    if (lane < 8)       bl = lane * ASTRIDE_W;
    else if (lane < 16) bl = (lane - 8) * ASTRIDE_W + 4;
    else if (lane < 24) bl = (lane - 8) * ASTRIDE_W;
    else                bl = (lane - 16) * ASTRIDE_W + 4;
    const int boff = (warp_n * 64 * ASTRIDE_W + bl) * 4;
    const unsigned int aLd = sA0 + aoff;
    const unsigned int bLd = sB0 + boff;

    #define ISSUE(kkv) {                                                        \
        const int _b  = (kkv) & 3;                                              \
        const int _kb = (kkv) & 31;                                             \
        const int _ct = (kkv) >> 5;                                             \
        if (doA) cp_async16(aSt + _b * (A_BUFW * 4), Asrc + _kb * 8);           \
        cp_async16(bSt + _b * (B_BUFW * 4),                                     \
                   Bsrc0 + (size_t)_ct * (128 * (WDIM / 2)) + _kb * 8);         \
        asm volatile("cp.async.commit_group;");                                 \
    }

    unsigned long long umin[2];
    umin[0] = 0xFFFFFFFFFFFFFFFFull;
    umin[1] = 0xFFFFFFFFFFFFFFFFull;

    ISSUE(0); ISSUE(1); ISSUE(2);

    int kk = 0;
    for (int ct = 0; ct < 8; ct++) {
        float acc[8][4];
        #pragma unroll
        for (int ni = 0; ni < 8; ni++)
            #pragma unroll
            for (int q = 0; q < 4; q++) acc[ni][q] = 0.0f;

        #pragma unroll 1
        for (int kb = 0; kb < 32; kb++, kk++) {
            if (kk < 254)       asm volatile("cp.async.wait_group 2;");
            else if (kk == 254) asm volatile("cp.async.wait_group 1;");
            else                asm volatile("cp.async.wait_group 0;");
            __syncthreads();
            if (kk + 3 < 256) ISSUE(kk + 3);

            const int cur = kk & 3;
            unsigned int af[4], bf[4][4];
            ldsm_x4(af[0], af[1], af[2], af[3], aLd + cur * (A_BUFW * 4));
            #pragma unroll
            for (int p = 0; p < 4; p++)
                ldsm_x4(bf[p][0], bf[p][1], bf[p][2], bf[p][3],
                        bLd + cur * (B_BUFW * 4) + p * 16 * ASTRIDE_W * 4);
            #pragma unroll
            for (int ni = 0; ni < 8; ni++)
                mma_bf16(acc[ni], af, bf[ni >> 1][(ni & 1) * 2],
                         bf[ni >> 1][(ni & 1) * 2 + 1]);
        }

        // epilogue (registers/gmem only)
        const int cBase = cBase0 + ct * 128;
        #pragma unroll
        for (int ni = 0; ni < 8; ni++) {
            const int row0 = rBase + warp_m * 16 + g;
            const int col0 = cBase + warp_n * 64 + ni * 8 + tig * 2;
            const float2 kn = *(const float2*)&g_knorm[col0];
            float2 o0, o1;
            o0.x = fmaf(-2.0f, acc[ni][0], kn.x);
            o0.y = fmaf(-2.0f, acc[ni][1], kn.y);
            o1.x = fmaf(-2.0f, acc[ni][2], kn.x);
            o1.y = fmaf(-2.0f, acc[ni][3], kn.y);
            g_distb[(size_t)row0 * (KC / 2) + (col0 >> 1)]       = pk_bf16x2(o0.x, o0.y);
            g_distb[(size_t)(row0 + 8) * (KC / 2) + (col0 >> 1)] = pk_bf16x2(o1.x, o1.y);
            unsigned long long k0 =
                ((unsigned long long)fmono(o0.x) << 32) | (unsigned)col0;
            unsigned long long k1 =
                ((unsigned long long)fmono(o0.y) << 32) | (unsigned)(col0 + 1);
            unsigned long long k2 =
                ((unsigned long long)fmono(o1.x) << 32) | (unsigned)col0;
            unsigned long long k3 =
                ((unsigned long long)fmono(o1.y) << 32) | (unsigned)(col0 + 1);
            if (k1 < k0) k0 = k1;
            if (k0 < umin[0]) umin[0] = k0;
            if (k3 < k2) k2 = k3;
            if (k2 < umin[1]) umin[1] = k2;
        }
    }
    #undef ISSUE

    #pragma unroll
    for (int h = 0; h < 2; h++) {
        unsigned long long key = umin[h];
        unsigned long long o;
        o = __shfl_xor_sync(0xffffffffu, key, 1); if (o < key) key = o;
        o = __shfl_xor_sync(0xffffffffu, key, 2); if (o < key) key = o;
        if (tig == 0) {
            const int row = rBase + warp_m * 16 + h * 8 + g;
            atomicMin(&g_best[row], key);
        }
    }
}

// ================= kernel 3b: candidate scan + exact fp32 rescore ===========
__global__ void __launch_bounds__(256) vq_select_kernel(const float* __restrict__ kmat,
                                                        float* __restrict__ out_xl) {
    __shared__ float  sx[8][512];
    __shared__ double sfit[8];
    const int lane = threadIdx.x & 31;
    const int warp = threadIdx.x >> 5;
    const int row  = blockIdx.x * 8 + warp;

    const float4* xr4 = (const float4*)(g_xf + (size_t)row * WDIM);
    float4* sx4 = (float4*)sx[warp];
    #pragma unroll
    for (int j = lane; j < 128; j += 32) sx4[j] = xr4[j];
    __syncwarp();

    const float rn   = g_rownorm[row];
    const float thrb = fmono_inv((unsigned)(g_best[row] >> 32)) + EPSM + BSLACK;
    const uint4* dr4 = (const uint4*)(g_distb + (size_t)row * (KC / 2));

    unsigned long long bkey = 0xFFFFFFFFFFFFFFFFull;
    #pragma unroll 1
    for (int j = 0; j < 8; j++) {
        uint4 v = dr4[j * 32 + lane];
        const int wbase = j * 128 + lane * 4;
        #pragma unroll
        for (int c = 0; c < 4; c++) {
            unsigned int wbits = (c == 0) ? v.x : (c == 1) ? v.y : (c == 2) ? v.z : v.w;
            float dlo = __uint_as_float(wbits << 16);
            float dhi = __uint_as_float(wbits & 0xFFFF0000u);
            #pragma unroll
            for (int h = 0; h < 2; h++) {
                float dv = h ? dhi : dlo;
                if (dv <= thrb) {
                    const int idx = (wbase + c) * 2 + h;
                    const float4* kr4 = (const float4*)(kmat + (size_t)idx * WDIM);
                    float acc = 0.0f;
                    #pragma unroll 4
                    for (int w = 0; w < 128; w++) {
                        float4 xv = sx4[w];
                        float4 kv = kr4[w];
                        acc = fmaf(xv.x, kv.x, acc);
                        acc = fmaf(xv.y, kv.y, acc);
                        acc = fmaf(xv.z, kv.z, acc);
                        acc = fmaf(xv.w, kv.w, acc);
                    }
                    float dist = __fadd_rn(__fadd_rn(rn, -__fmul_rn(2.0f, acc)), g_knorm[idx]);
                    unsigned long long k2 =
                        ((unsigned long long)fmono(dist) << 32) | (unsigned)idx;
                    if (k2 < bkey) bkey = k2;
                }
            }
        }
    }
    #pragma unroll
    for (int o = 16; o > 0; o >>= 1) {
        unsigned long long other = __shfl_xor_sync(0xffffffffu, bkey, o);
        if (other < bkey) bkey = other;
    }
    if (lane == 0) {
        const int idx = (int)(unsigned)(bkey & 0xFFFFFFFFull);
        const float dist = fmono_inv((unsigned)(bkey >> 32));
        g_xl[row] = idx;
        out_xl[row] = (float)idx;
        sfit[warp] = (double)dist;
    }
    __syncthreads();
    if (threadIdx.x == 0) {
        double s = 0.0;
        #pragma unroll
        for (int j = 0; j < 8; j++) s += sfit[j];
        atomicAdd(&g_red[2], s);   // fit sum
    }
}

// ================= kernel R1: bucket scatter (counting-sort rank) ===========
__global__ void vq_bucket_kernel() {
    const int round = blockIdx.y;
    const int i = blockIdx.x * 256 + threadIdx.x;
    const unsigned int key = g_sk[round][i];
    const int b = key >> 21;
    const int pos = atomicAdd(&g_cnt[round][b], 1);
    g_mem[round][b * MAXB + pos] = i;
}

// ================= kernel R2: bucket exclusive prefix sums ==================
__global__ void vq_prefix_kernel() {
    __shared__ int part[256];
    const int round = blockIdx.x;
    const int t = threadIdx.x;   // 256
    int s = 0;
    int loc[8];
    #pragma unroll
    for (int j = 0; j < 8; j++) { loc[j] = s; s += g_cnt[round][t * 8 + j]; }
    part[t] = s;
    __syncthreads();
    if (t == 0) {
        int run = 0;
        for (int j = 0; j < 256; j++) { int v = part[j]; part[j] = run; run += v; }
    }
    __syncthreads();
    const int base = part[t];
    #pragma unroll
    for (int j = 0; j < 8; j++) g_basep[round][t * 8 + j] = base + loc[j];
}

// ================= kernel R3: exact stable rank within bucket ===============
__global__ void vq_rank_kernel(int round) {
    const int i = blockIdx.x * 256 + threadIdx.x;
    const unsigned int key = g_sk[round][i];
    const int b = key >> 21;
    const int cnt = g_cnt[round][b];
    const int* mem = &g_mem[round][b * MAXB];
    int r = g_basep[round][b];
    for (int p = 0; p < cnt; p++) {
        const int j = mem[p];
        const unsigned int kj = g_sk[round][j];
        r += (kj < key || (kj == key && j < i)) ? 1 : 0;
    }
    if (round == 0) g_v1[r] = i;            // round-1: sorted_val[rank] = i
    else            g_ind[r] = g_v1[i];     // round-2: k_rand[j] = xf[g_ind[j]]
}

// ================= kernel 4: x_d[n,w,t] = k[x_l[n*T+t], w] =================
__global__ void vq_xd_kernel(const float* __restrict__ kmat, float* __restrict__ out_xd) {
    __shared__ int   sj[32];
    __shared__ float kk[32][33];
    const int n  = blockIdx.z;
    const int w0 = blockIdx.y * 32;
    const int t0 = blockIdx.x * 32;
    const int tx = threadIdx.x;
    const int ty = threadIdx.y;
    if (ty == 0) sj[tx] = g_xl[n * TB + t0 + tx];
    __syncthreads();
    kk[ty][tx] = kmat[(size_t)sj[ty] * WDIM + w0 + tx];
    __syncthreads();
    out_xd[((size_t)n * WDIM + w0 + ty) * TB + t0 + tx] = kk[tx][ty];
}

// ================= kernel 5: scatter cluster stats + commit loss ============
__global__ void vq_scatter_kernel(const float* __restrict__ kmat) {
    const int lane = threadIdx.x & 31;
    const int warp = threadIdx.x >> 5;
    const int row  = blockIdx.x * 8 + warp;
    if (row >= NT) return;
    const int j = g_xl[row];
    const float* xr = g_xf + (size_t)row * WDIM;
    const float* kr = kmat + (size_t)j * WDIM;
    float c = 0.0f;
    for (int w = lane; w < WDIM; w += 32) {
        float xv = xr[w];
        atomicAdd(&g_ksum_acc[(size_t)j * WDIM + w], xv);
        float d = xv - kr[w];
        c += d * d;
    }
    c = warp_sum(c);
    if (lane == 0) {
        atomicAdd(&g_red[3], (double)c);
        atomicAdd(&g_kelem_acc[j], 1.0f);
    }
}

// ================= kernel 6: EMA update, k_new, dk =================
__global__ void vq_knew_kernel(const float* __restrict__ kmat,
                               const float* __restrict__ ksum_in,
                               const float* __restrict__ kelem_in,
                               float* __restrict__ out_knew,
                               float* __restrict__ out_ksumnew,
                               float* __restrict__ out_kelemnew) {
    __shared__ float s_en;
    __shared__ float sred[4];
    const int j = blockIdx.x;
    const int tid = threadIdx.x;  // 128
    if (tid == 0) {
        float en = __fadd_rn(__fmul_rn(MU_F, kelem_in[j]), __fmul_rn(OMM_F, g_kelem_acc[j]));
        s_en = en;
        out_kelemnew[j] = en;
    }
    __syncthreads();
    const float en = s_en;
    const bool usage = (en >= 1.0f);   // THRESHOLD=1.0
    const float* krand_row = g_xf + (size_t)g_ind[j] * WDIM;
    float dks = 0.0f;
    for (int w = tid; w < WDIM; w += 128) {
        size_t idx = (size_t)j * WDIM + w;
        float ksn = __fadd_rn(__fmul_rn(MU_F, ksum_in[idx]), __fmul_rn(OMM_F, g_ksum_acc[idx]));
        out_ksumnew[idx] = ksn;
        float kn = usage ? __fdiv_rn(ksn, en) : krand_row[w];
        out_knew[idx] = kn;
        float d = kn - kmat[idx];
        dks += d * d;
    }
    dks = warp_sum(dks);
    if ((tid & 31) == 0) sred[tid >> 5] = dks;
    __syncthreads();
    if (tid == 0) {
        float t = sred[0] + sred[1] + sred[2] + sred[3];
        atomicAdd(&g_red[4], (double)t);
    }
}

// ================= kernel 7: scalars =================
__global__ void vq_final_kernel(float* __restrict__ o_scal) {
    __shared__ double sE[8];
    const int tid = threadIdx.x;   // 256
    double le = 0.0;
    for (int j = tid; j < KC; j += 256) {
        float cnt = g_kelem_acc[j];
        float p = __fdiv_rn(cnt, 16384.0f);
        le += (double)(p * logf(__fadd_rn(p, 1e-8f)));
    }
    le = warp_sum_d(le);
    if ((tid & 31) == 0) sE[tid >> 5] = le;
    __syncthreads();
    if (tid == 0) {
        double ent = 0.0;
        #pragma unroll
        for (int j = 0; j < 8; j++) ent += sE[j];
        const double SZ = (double)NT * (double)WDIM;
        double mean = g_red[0] / SZ;
        o_scal[0] = (float)(g_red[3] / SZ);                    // commit_loss
        o_scal[1] = (float)(g_red[2] / (double)NT);            // fit
        o_scal[2] = (float)sqrt(g_red[1] / SZ - mean * mean);  // prenorm
        o_scal[3] = (float)(-ent);                             // entropy
        o_scal[4] = (float)(sqrt(g_red[4]) / 1024.0);          // dk
    }
}

// ================= launch =================
extern "C" void kernel_launch(void* const* d_in, const int* in_sizes, int n_in,
                              void* d_out, int out_size) {
    (void)in_sizes; (void)n_in; (void)out_size;
    const float* x     = (const float*)d_in[0];   // [16,512,1024]
    const float* k     = (const float*)d_in[1];   // [2048,512]
    const float* ksum  = (const float*)d_in[2];   // [2048,512]
    const float* kelem = (const float*)d_in[3];   // [2048]
    float* out = (float*)d_out;

    // heavy kernels first so the ncu capture slot lands on vq_dist_kernel
    vq_zero_kernel<<<1024, 256>>>();
    vq_transpose_kernel<<<dim3(TB / 32, WDIM / 32, NB), dim3(32, 8)>>>(x);
    vq_knorm_kernel<<<KC / 4, 128>>>(k);
    vq_dist_kernel<<<dim3(NT / 64, 2), 256>>>();
    vq_select_kernel<<<NT / 8, 256>>>(k, out + O_XL);
    // permutation machinery (counting-sort rank, exact stable order)
    vq_bucket_kernel<<<dim3(NT / 256, 2), 256>>>();
    vq_prefix_kernel<<<2, 256>>>();
    vq_rank_kernel<<<NT / 256, 256>>>(0);
    vq_rank_kernel<<<NT / 256, 256>>>(1);
    // outputs
    vq_xd_kernel<<<dim3(TB / 32, WDIM / 32, NB), dim3(32, 32)>>>(k, out + O_XD);
    vq_scatter_kernel<<<NT / 8, 256>>>(k);
    vq_knew_kernel<<<KC, 128>>>(k, ksum, kelem,
                                out + O_KNEW, out + O_KSUM, out + O_KELEM);
    vq_final_kernel<<<1, 256>>>(out + O_SCAL);
}

// round 17
// speedup vs baseline: 1.1094x; 1.1094x over previous
#include <cuda_runtime.h>
#include <cuda_bf16.h>
#include <math.h>

// Problem dims (fixed by the reference)
#define NT    16384          // N*T rows
#define WDIM  512            // feature dim
#define KC    2048           // codebook size
#define NB    16             // N
#define TB    1024           // T

#define MU_F   0.99f
#define OMM_F  ((float)(1.0 - 0.99))   // exact JAX constant
#define EPSM   0.125f                  // candidate margin >> bf16 dist error (~0.02 worst)
#define BSLACK 0.03125f                // extra slack for bf16-stored dist rounding
#define MAXB   64                      // max bucket occupancy (Poisson(8); P(>64) ~ 0)

// Output layout (tuple flattened, float32)
#define O_XL     0
#define O_XD     16384
#define O_SCAL   8404992
#define O_KNEW   8404997
#define O_KSUM   9453573
#define O_KELEM  10502149

// -------- scratch (static device globals) --------
__device__ float  g_xf[(size_t)NT * WDIM];
__device__ unsigned int g_xfh[(size_t)NT * (WDIM / 2)];  // bf16x2 copy of xf
__device__ unsigned int g_kh[(size_t)KC * (WDIM / 2)];   // bf16x2 copy of k
__device__ float  g_rownorm[NT];
__device__ float  g_knorm[KC];
__device__ int    g_xl[NT];
__device__ unsigned long long g_best[NT];        // approx (monotone distbits)<<32 | idx
__device__ unsigned int g_distb[(size_t)NT * (KC / 2)];  // 64 MiB bf16x2 approx dist
__device__ float  g_ksum_acc[(size_t)KC * WDIM];
__device__ float  g_kelem_acc[KC];
__device__ double g_red[8];                      // 0 sum, 1 sumsq, 2 fit, 3 commit, 4 dk
// permutation machinery (jax.random.permutation(key(42), xf) reproduction)
__device__ unsigned int g_sk[2][NT];
__device__ int    g_cnt[2][2048];                // bucket counts
__device__ int    g_basep[2][2048];              // bucket exclusive prefix
__device__ int    g_mem[2][2048 * MAXB];         // bucket member lists
__device__ int    g_v1[NT];
__device__ int    g_ind[NT];

// -------- helpers --------
__device__ __forceinline__ float warp_sum(float v) {
    #pragma unroll
    for (int o = 16; o > 0; o >>= 1) v += __shfl_xor_sync(0xffffffffu, v, o);
    return v;
}
__device__ __forceinline__ double warp_sum_d(double v) {
    #pragma unroll
    for (int o = 16; o > 0; o >>= 1) v += __shfl_xor_sync(0xffffffffu, v, o);
    return v;
}

// monotone float->uint map (order-preserving for all finite floats)
__device__ __forceinline__ unsigned int fmono(float f) {
    unsigned int b = __float_as_uint(f);
    return (b & 0x80000000u) ? ~b : (b | 0x80000000u);
}
__device__ __forceinline__ float fmono_inv(unsigned int u) {
    unsigned int b = (u & 0x80000000u) ? (u & 0x7FFFFFFFu) : ~u;
    return __uint_as_float(b);
}

// pack two f32 into bf16x2 (lo -> low 16 bits, hi -> high 16 bits), round-to-nearest
__device__ __forceinline__ unsigned int pk_bf16x2(float lo, float hi) {
    unsigned int w;
    asm("cvt.rn.bf16x2.f32 %0, %1, %2;" : "=r"(w) : "f"(hi), "f"(lo));
    return w;
}

// 16-byte async global->shared copy
__device__ __forceinline__ void cp_async16(unsigned int saddr, const void* gptr) {
    asm volatile("cp.async.ca.shared.global [%0], [%1], 16;"
                 :: "r"(saddr), "l"(gptr));
}

// ldmatrix x4 (b16, non-transposed)
__device__ __forceinline__ void ldsm_x4(unsigned int& r0, unsigned int& r1,
                                        unsigned int& r2, unsigned int& r3,
                                        unsigned int saddr) {
    asm volatile("ldmatrix.sync.aligned.m8n8.x4.shared.b16 {%0,%1,%2,%3}, [%4];"
                 : "=r"(r0), "=r"(r1), "=r"(r2), "=r"(r3) : "r"(saddr));
}

// m16n8k16 bf16 mma, D += A*B
__device__ __forceinline__ void mma_bf16(float* d, const unsigned int* a,
                                         unsigned int b0, unsigned int b1) {
    asm volatile(
        "mma.sync.aligned.m16n8k16.row.col.f32.bf16.bf16.f32 "
        "{%0,%1,%2,%3}, {%4,%5,%6,%7}, {%8,%9}, {%0,%1,%2,%3};"
        : "+f"(d[0]), "+f"(d[1]), "+f"(d[2]), "+f"(d[3])
        : "r"(a[0]), "r"(a[1]), "r"(a[2]), "r"(a[3]), "r"(b0), "r"(b1));
}

// -------- Threefry-2x32 (exact JAX cipher) --------
#define TF_ROUND(x0, x1, r) { x0 += x1; x1 = ((x1) << (r)) | ((x1) >> (32 - (r))); x1 ^= x0; }

__device__ __forceinline__ uint2 threefry2x32(unsigned int k0, unsigned int k1,
                                              unsigned int x0, unsigned int x1) {
    unsigned int k2 = k0 ^ k1 ^ 0x1BD11BDAu;
    x0 += k0; x1 += k1;
    TF_ROUND(x0, x1, 13) TF_ROUND(x0, x1, 15) TF_ROUND(x0, x1, 26) TF_ROUND(x0, x1, 6)
    x0 += k1; x1 += k2 + 1u;
    TF_ROUND(x0, x1, 17) TF_ROUND(x0, x1, 29) TF_ROUND(x0, x1, 16) TF_ROUND(x0, x1, 24)
    x0 += k2; x1 += k0 + 2u;
    TF_ROUND(x0, x1, 13) TF_ROUND(x0, x1, 15) TF_ROUND(x0, x1, 26) TF_ROUND(x0, x1, 6)
    x0 += k0; x1 += k1 + 3u;
    TF_ROUND(x0, x1, 17) TF_ROUND(x0, x1, 29) TF_ROUND(x0, x1, 16) TF_ROUND(x0, x1, 24)
    x0 += k1; x1 += k2 + 4u;
    TF_ROUND(x0, x1, 13) TF_ROUND(x0, x1, 15) TF_ROUND(x0, x1, 26) TF_ROUND(x0, x1, 6)
    x0 += k2; x1 += k0 + 5u;
    return make_uint2(x0, x1);
}

// ================= kernel 0: zero scratch + threefry sort keys ==============
__global__ void vq_zero_kernel() {
    int i = blockIdx.x * blockDim.x + threadIdx.x;
    int stride = gridDim.x * blockDim.x;
    for (int idx = i; idx < KC * WDIM; idx += stride) g_ksum_acc[idx] = 0.0f;
    for (int idx = i; idx < KC;        idx += stride) g_kelem_acc[idx] = 0.0f;
    for (int idx = i; idx < NT;        idx += stride) {
        g_rownorm[idx] = 0.0f;
        g_best[idx] = 0xFFFFFFFFFFFFFFFFull;
    }
    if (i < 2048) { g_cnt[0][i] = 0; g_cnt[1][i] = 0; }
    if (i < 8) g_red[i] = 0.0;
    if (i < NT) {
        uint2 k1 = threefry2x32(0u, 42u, 0u, 0u);
        uint2 s1 = threefry2x32(0u, 42u, 0u, 1u);
        uint2 s2 = threefry2x32(k1.x, k1.y, 0u, 1u);
        uint2 r1 = threefry2x32(s1.x, s1.y, 0u, (unsigned)i);
        g_sk[0][i] = r1.x ^ r1.y;
        uint2 r2 = threefry2x32(s2.x, s2.y, 0u, (unsigned)i);
        g_sk[1][i] = r2.x ^ r2.y;
    }
}

// ================= kernel 1: transpose x[N,W,T] -> xf[NT,W] (+bf16) + stats ==
__global__ void vq_transpose_kernel(const float* __restrict__ x) {
    __shared__ float tile[32][33];
    __shared__ float sWs[8], sWq[8];
    const int n  = blockIdx.z;
    const int w0 = blockIdx.y * 32;
    const int t0 = blockIdx.x * 32;
    const int tx = threadIdx.x;   // 32
    const int ty = threadIdx.y;   // 8

    float ls = 0.0f, lq = 0.0f;
    #pragma unroll
    for (int i = 0; i < 4; i++) {
        int wl = ty + i * 8;
        float v = x[((size_t)n * WDIM + (w0 + wl)) * TB + t0 + tx];
        tile[wl][tx] = v;
        ls += v;
        lq += v * v;
    }
    __syncthreads();
    #pragma unroll
    for (int i = 0; i < 4; i++) {
        int tl = ty + i * 8;
        float v = tile[tx][tl];                      // w = w0+tx, t = t0+tl
        const size_t row = (size_t)(n * TB + t0 + tl);
        g_xf[row * WDIM + w0 + tx] = v;
        float vn = __shfl_down_sync(0xffffffffu, v, 1);
        if ((tx & 1) == 0)
            g_xfh[(row * WDIM + w0 + tx) >> 1] = pk_bf16x2(v, vn);
        float s = warp_sum(v * v);
        if (tx == 0) atomicAdd(&g_rownorm[n * TB + t0 + tl], s);
    }
    ls = warp_sum(ls);
    lq = warp_sum(lq);
    if (tx == 0) { sWs[ty] = ls; sWq[ty] = lq; }
    __syncthreads();
    if (tx == 0 && ty == 0) {
        float a = 0.0f, b = 0.0f;
        #pragma unroll
        for (int j = 0; j < 8; j++) { a += sWs[j]; b += sWq[j]; }
        atomicAdd(&g_red[0], (double)a);
        atomicAdd(&g_red[1], (double)b);
    }
}

// ================= kernel 2: codebook row norms + bf16 copy =================
__global__ void vq_knorm_kernel(const float* __restrict__ kmat) {
    const int lane = threadIdx.x & 31;
    const int warp = threadIdx.x >> 5;
    const int c = blockIdx.x * 4 + warp;
    if (c >= KC) return;
    float s = 0.0f;
    for (int w = lane; w < WDIM; w += 32) {
        float v = kmat[(size_t)c * WDIM + w];
        s += v * v;
        float vn = __shfl_down_sync(0xffffffffu, v, 1);
        if ((lane & 1) == 0)
            g_kh[((size_t)c * WDIM + w) >> 1] = pk_bf16x2(v, vn);
    }
    s = warp_sum(s);
    if (lane == 0) g_knorm[c] = s;
}

// ================= kernel 3a: bf16 tensor-core dist GEMM (R15 config) =======
// 32x64 warp tile, 128 rows/block, 4-stage cp.async, one barrier per K-step,
// ldmatrix frag loads. Dist bits identical to the passing R13/R15 kernels.
__global__ void __launch_bounds__(256, 2) vq_dist_kernel() {
    __shared__ unsigned int As[4][128 * 12];   // 24 KiB
    __shared__ unsigned int Bs[4][128 * 12];   // 24 KiB

    const int tid  = threadIdx.x;
    const int lane = tid & 31;
    const int wid  = tid >> 5;
    const int warp_m = wid & 3;
    const int warp_n = wid >> 2;
    const int g   = lane >> 2;
    const int tig = lane & 3;
    const int rBase  = blockIdx.x * 128;
    const int cBase0 = blockIdx.y * 1024;

    const int srow = tid >> 1;            // staging row 0..127
    const int skw  = (tid & 1) * 4;       // staging word offset (0 or 4)
    const unsigned int* Asrc = g_xfh + (size_t)(rBase + srow) * (WDIM / 2) + skw;
    const unsigned int* Bsrc0 = g_kh + (size_t)(cBase0 + srow) * (WDIM / 2) + skw;

    unsigned int aAd[4], bAd[4];
    #pragma unroll
    for (int b = 0; b < 4; b++) {
        aAd[b] = (unsigned int)__cvta_generic_to_shared(&As[b][srow * 12 + skw]);
        bAd[b] = (unsigned int)__cvta_generic_to_shared(&Bs[b][srow * 12 + skw]);
    }

    const int abase_row = warp_m * 32;
    const int aoff = ((lane < 16) ? (abase_row + lane) * 12
                                  : (abase_row + lane - 16) * 12 + 4) * 4;
    int bl;
    if (lane < 8)       bl = lane * 12;
    else if (lane < 16) bl = (lane - 8) * 12 + 4;
    else if (lane < 24) bl = (lane - 8) * 12;
    else                bl = (lane - 16) * 12 + 4;
    const int boff = (warp_n * 64 * 12 + bl) * 4;

    unsigned int aBuf[4], bBuf[4];
    #pragma unroll
    for (int b = 0; b < 4; b++) {
        aBuf[b] = (unsigned int)__cvta_generic_to_shared(&As[b][0]) + aoff;
        bBuf[b] = (unsigned int)__cvta_generic_to_shared(&Bs[b][0]) + boff;
    }

    #define ISSUE(kkv) {                                                        \
        const int _b  = (kkv) & 3;                                              \
        const int _kb = (kkv) & 31;                                             \
        const int _ct = (kkv) >> 5;                                             \
        cp_async16(aAd[_b], Asrc + _kb * 8);                                    \
        cp_async16(bAd[_b], Bsrc0 + (size_t)_ct * (128 * (WDIM / 2)) + _kb * 8);\
        asm volatile("cp.async.commit_group;");                                 \
    }

    unsigned long long umin[2][2];
    #pragma unroll
    for (int a = 0; a < 2; a++)
        #pragma unroll
        for (int b = 0; b < 2; b++) umin[a][b] = 0xFFFFFFFFFFFFFFFFull;

    ISSUE(0); ISSUE(1); ISSUE(2);

    int kk = 0;
    for (int ct = 0; ct < 8; ct++) {
        float acc[2][8][4];
        #pragma unroll
        for (int mi = 0; mi < 2; mi++)
            #pragma unroll
            for (int ni = 0; ni < 8; ni++)
                #pragma unroll
                for (int q = 0; q < 4; q++) acc[mi][ni][q] = 0.0f;

        #pragma unroll 1
        for (int kb = 0; kb < 32; kb++, kk++) {
            if (kk < 254)       asm volatile("cp.async.wait_group 2;");
            else if (kk == 254) asm volatile("cp.async.wait_group 1;");
            else                asm volatile("cp.async.wait_group 0;");
            __syncthreads();
            if (kk + 3 < 256) ISSUE(kk + 3);

            const int cur = kk & 3;
            unsigned int af[2][4], bf[4][4];
            ldsm_x4(af[0][0], af[0][1], af[0][2], af[0][3], aBuf[cur]);
            ldsm_x4(af[1][0], af[1][1], af[1][2], af[1][3], aBuf[cur] + 16 * 12 * 4);
            #pragma unroll
            for (int p = 0; p < 4; p++)
                ldsm_x4(bf[p][0], bf[p][1], bf[p][2], bf[p][3],
                        bBuf[cur] + p * 16 * 12 * 4);
            #pragma unroll
            for (int ni = 0; ni < 8; ni++) {
                const unsigned int b0 = bf[ni >> 1][(ni & 1) * 2];
                const unsigned int b1 = bf[ni >> 1][(ni & 1) * 2 + 1];
                mma_bf16(acc[0][ni], af[0], b0, b1);
                mma_bf16(acc[1][ni], af[1], b0, b1);
            }
        }

        // epilogue (registers/gmem only)
        const int cBase = cBase0 + ct * 128;
        #pragma unroll
        for (int mi = 0; mi < 2; mi++) {
            #pragma unroll
            for (int ni = 0; ni < 8; ni++) {
                const int row0 = rBase + warp_m * 32 + mi * 16 + g;
                const int col0 = cBase + warp_n * 64 + ni * 8 + tig * 2;
                const float2 kn = *(const float2*)&g_knorm[col0];
                float2 o0, o1;
                o0.x = fmaf(-2.0f, acc[mi][ni][0], kn.x);
                o0.y = fmaf(-2.0f, acc[mi][ni][1], kn.y);
                o1.x = fmaf(-2.0f, acc[mi][ni][2], kn.x);
                o1.y = fmaf(-2.0f, acc[mi][ni][3], kn.y);
                g_distb[(size_t)row0 * (KC / 2) + (col0 >> 1)]       = pk_bf16x2(o0.x, o0.y);
                g_distb[(size_t)(row0 + 8) * (KC / 2) + (col0 >> 1)] = pk_bf16x2(o1.x, o1.y);
                unsigned long long k0 =
                    ((unsigned long long)fmono(o0.x) << 32) | (unsigned)col0;
                unsigned long long k1 =
                    ((unsigned long long)fmono(o0.y) << 32) | (unsigned)(col0 + 1);
                unsigned long long k2 =
                    ((unsigned long long)fmono(o1.x) << 32) | (unsigned)col0;
                unsigned long long k3 =
                    ((unsigned long long)fmono(o1.y) << 32) | (unsigned)(col0 + 1);
                if (k1 < k0) k0 = k1;
                if (k0 < umin[mi][0]) umin[mi][0] = k0;
                if (k3 < k2) k2 = k3;
                if (k2 < umin[mi][1]) umin[mi][1] = k2;
            }
        }
    }
    #undef ISSUE

    #pragma unroll
    for (int mi = 0; mi < 2; mi++) {
        #pragma unroll
        for (int h = 0; h < 2; h++) {
            unsigned long long key = umin[mi][h];
            unsigned long long o;
            o = __shfl_xor_sync(0xffffffffu, key, 1); if (o < key) key = o;
            o = __shfl_xor_sync(0xffffffffu, key, 2); if (o < key) key = o;
            if (tig == 0) {
                const int row = rBase + warp_m * 32 + mi * 16 + h * 8 + g;
                atomicMin(&g_best[row], key);
            }
        }
    }
}

// ====== kernel 3b: candidate scan + exact fp32 rescore + FUSED scatter ======
// After selecting the winner, the warp (with the xf row already in smem)
// performs the cluster-stat scatter and commit-loss accumulation that
// previously required a separate 32MB pass (vq_scatter_kernel).
__global__ void __launch_bounds__(256) vq_select_kernel(const float* __restrict__ kmat,
                                                        float* __restrict__ out_xl) {
    __shared__ float  sx[8][512];
    __shared__ double sfit[8];
    __shared__ double scom[8];
    const int lane = threadIdx.x & 31;
    const int warp = threadIdx.x >> 5;
    const int row  = blockIdx.x * 8 + warp;

    const float4* xr4 = (const float4*)(g_xf + (size_t)row * WDIM);
    float4* sx4 = (float4*)sx[warp];
    #pragma unroll
    for (int j = lane; j < 128; j += 32) sx4[j] = xr4[j];
    __syncwarp();

    const float rn   = g_rownorm[row];
    const float thrb = fmono_inv((unsigned)(g_best[row] >> 32)) + EPSM + BSLACK;
    const uint4* dr4 = (const uint4*)(g_distb + (size_t)row * (KC / 2));

    unsigned long long bkey = 0xFFFFFFFFFFFFFFFFull;
    #pragma unroll 1
    for (int j = 0; j < 8; j++) {
        uint4 v = dr4[j * 32 + lane];
        const int wbase = j * 128 + lane * 4;
        #pragma unroll
        for (int c = 0; c < 4; c++) {
            unsigned int wbits = (c == 0) ? v.x : (c == 1) ? v.y : (c == 2) ? v.z : v.w;
            float dlo = __uint_as_float(wbits << 16);
            float dhi = __uint_as_float(wbits & 0xFFFF0000u);
            #pragma unroll
            for (int h = 0; h < 2; h++) {
                float dv = h ? dhi : dlo;
                if (dv <= thrb) {
                    const int idx = (wbase + c) * 2 + h;
                    const float4* kr4 = (const float4*)(kmat + (size_t)idx * WDIM);
                    float acc = 0.0f;
                    #pragma unroll 4
                    for (int w = 0; w < 128; w++) {
                        float4 xv = sx4[w];
                        float4 kv = kr4[w];
                        acc = fmaf(xv.x, kv.x, acc);
                        acc = fmaf(xv.y, kv.y, acc);
                        acc = fmaf(xv.z, kv.z, acc);
                        acc = fmaf(xv.w, kv.w, acc);
                    }
                    float dist = __fadd_rn(__fadd_rn(rn, -__fmul_rn(2.0f, acc)), g_knorm[idx]);
                    unsigned long long k2 =
                        ((unsigned long long)fmono(dist) << 32) | (unsigned)idx;
                    if (k2 < bkey) bkey = k2;
                }
            }
        }
    }
    #pragma unroll
    for (int o = 16; o > 0; o >>= 1) {
        unsigned long long other = __shfl_xor_sync(0xffffffffu, bkey, o);
        if (other < bkey) bkey = other;
    }
    const int widx = (int)(unsigned)(bkey & 0xFFFFFFFFull);   // warp-uniform winner
    if (lane == 0) {
        g_xl[row] = widx;
        out_xl[row] = (float)widx;
        sfit[warp] = (double)fmono_inv((unsigned)(bkey >> 32));
    }

    // fused scatter: cluster sums + commit loss (xf row already in smem)
    {
        const float* xr = sx[warp];
        const float* kr = kmat + (size_t)widx * WDIM;
        float c = 0.0f;
        #pragma unroll 4
        for (int w = lane; w < WDIM; w += 32) {
            float xv = xr[w];
            atomicAdd(&g_ksum_acc[(size_t)widx * WDIM + w], xv);
            float d = xv - kr[w];
            c += d * d;
        }
        c = warp_sum(c);
        if (lane == 0) {
            scom[warp] = (double)c;
            atomicAdd(&g_kelem_acc[widx], 1.0f);
        }
    }
    __syncthreads();
    if (threadIdx.x == 0) {
        double s = 0.0, cm = 0.0;
        #pragma unroll
        for (int j = 0; j < 8; j++) { s += sfit[j]; cm += scom[j]; }
        atomicAdd(&g_red[2], s);    // fit sum
        atomicAdd(&g_red[3], cm);   // commit sum
    }
}

// ================= kernel R1: bucket scatter (counting-sort rank) ===========
__global__ void vq_bucket_kernel() {
    const int round = blockIdx.y;
    const int i = blockIdx.x * 256 + threadIdx.x;
    const unsigned int key = g_sk[round][i];
    const int b = key >> 21;
    const int pos = atomicAdd(&g_cnt[round][b], 1);
    g_mem[round][b * MAXB + pos] = i;
}

// ================= kernel R2: bucket exclusive prefix sums ==================
__global__ void vq_prefix_kernel() {
    __shared__ int part[256];
    const int round = blockIdx.x;
    const int t = threadIdx.x;   // 256
    int s = 0;
    int loc[8];
    #pragma unroll
    for (int j = 0; j < 8; j++) { loc[j] = s; s += g_cnt[round][t * 8 + j]; }
    part[t] = s;
    __syncthreads();
    if (t == 0) {
        int run = 0;
        for (int j = 0; j < 256; j++) { int v = part[j]; part[j] = run; run += v; }
    }
    __syncthreads();
    const int base = part[t];
    #pragma unroll
    for (int j = 0; j < 8; j++) g_basep[round][t * 8 + j] = base + loc[j];
}

// ================= kernel R3: exact stable rank within bucket ===============
__global__ void vq_rank_kernel(int round) {
    const int i = blockIdx.x * 256 + threadIdx.x;
    const unsigned int key = g_sk[round][i];
    const int b = key >> 21;
    const int cnt = g_cnt[round][b];
    const int* mem = &g_mem[round][b * MAXB];
    int r = g_basep[round][b];
    for (int p = 0; p < cnt; p++) {
        const int j = mem[p];
        const unsigned int kj = g_sk[round][j];
        r += (kj < key || (kj == key && j < i)) ? 1 : 0;
    }
    if (round == 0) g_v1[r] = i;            // round-1: sorted_val[rank] = i
    else            g_ind[r] = g_v1[i];     // round-2: k_rand[j] = xf[g_ind[j]]
}

// ================= kernel 4: x_d[n,w,t] = k[x_l[n*T+t], w] =================
__global__ void vq_xd_kernel(const float* __restrict__ kmat, float* __restrict__ out_xd) {
    __shared__ int   sj[32];
    __shared__ float kk[32][33];
    const int n  = blockIdx.z;
    const int w0 = blockIdx.y * 32;
    const int t0 = blockIdx.x * 32;
    const int tx = threadIdx.x;
    const int ty = threadIdx.y;
    if (ty == 0) sj[tx] = g_xl[n * TB + t0 + tx];
    __syncthreads();
    kk[ty][tx] = kmat[(size_t)sj[ty] * WDIM + w0 + tx];
    __syncthreads();
    out_xd[((size_t)n * WDIM + w0 + ty) * TB + t0 + tx] = kk[tx][ty];
}

// ================= kernel 6: EMA update, k_new, dk =================
__global__ void vq_knew_kernel(const float* __restrict__ kmat,
                               const float* __restrict__ ksum_in,
                               const float* __restrict__ kelem_in,
                               float* __restrict__ out_knew,
                               float* __restrict__ out_ksumnew,
                               float* __restrict__ out_kelemnew) {
    __shared__ float s_en;
    __shared__ float sred[4];
    const int j = blockIdx.x;
    const int tid = threadIdx.x;  // 128
    if (tid == 0) {
        float en = __fadd_rn(__fmul_rn(MU_F, kelem_in[j]), __fmul_rn(OMM_F, g_kelem_acc[j]));
        s_en = en;
        out_kelemnew[j] = en;
    }
    __syncthreads();
    const float en = s_en;
    const bool usage = (en >= 1.0f);   // THRESHOLD=1.0
    const float* krand_row = g_xf + (size_t)g_ind[j] * WDIM;
    float dks = 0.0f;
    for (int w = tid; w < WDIM; w += 128) {
        size_t idx = (size_t)j * WDIM + w;
        float ksn = __fadd_rn(__fmul_rn(MU_F, ksum_in[idx]), __fmul_rn(OMM_F, g_ksum_acc[idx]));
        out_ksumnew[idx] = ksn;
        float kn = usage ? __fdiv_rn(ksn, en) : krand_row[w];
        out_knew[idx] = kn;
        float d = kn - kmat[idx];
        dks += d * d;
    }
    dks = warp_sum(dks);
    if ((tid & 31) == 0) sred[tid >> 5] = dks;
    __syncthreads();
    if (tid == 0) {
        float t = sred[0] + sred[1] + sred[2] + sred[3];
        atomicAdd(&g_red[4], (double)t);
    }
}

// ================= kernel 7: scalars =================
__global__ void vq_final_kernel(float* __restrict__ o_scal) {
    __shared__ double sE[8];
    const int tid = threadIdx.x;   // 256
    double le = 0.0;
    for (int j = tid; j < KC; j += 256) {
        float cnt = g_kelem_acc[j];
        float p = __fdiv_rn(cnt, 16384.0f);
        le += (double)(p * logf(__fadd_rn(p, 1e-8f)));
    }
    le = warp_sum_d(le);
    if ((tid & 31) == 0) sE[tid >> 5] = le;
    __syncthreads();
    if (tid == 0) {
        double ent = 0.0;
        #pragma unroll
        for (int j = 0; j < 8; j++) ent += sE[j];
        const double SZ = (double)NT * (double)WDIM;
        double mean = g_red[0] / SZ;
        o_scal[0] = (float)(g_red[3] / SZ);                    // commit_loss
        o_scal[1] = (float)(g_red[2] / (double)NT);            // fit
        o_scal[2] = (float)sqrt(g_red[1] / SZ - mean * mean);  // prenorm
        o_scal[3] = (float)(-ent);                             // entropy
        o_scal[4] = (float)(sqrt(g_red[4]) / 1024.0);          // dk
    }
}

// ================= launch =================
extern "C" void kernel_launch(void* const* d_in, const int* in_sizes, int n_in,
                              void* d_out, int out_size) {
    (void)in_sizes; (void)n_in; (void)out_size;
    const float* x     = (const float*)d_in[0];   // [16,512,1024]
    const float* k     = (const float*)d_in[1];   // [2048,512]
    const float* ksum  = (const float*)d_in[2];   // [2048,512]
    const float* kelem = (const float*)d_in[3];   // [2048]
    float* out = (float*)d_out;

    // heavy kernels first so the ncu capture slot lands on vq_dist_kernel
    vq_zero_kernel<<<1024, 256>>>();
    vq_transpose_kernel<<<dim3(TB / 32, WDIM / 32, NB), dim3(32, 8)>>>(x);
    vq_knorm_kernel<<<KC / 4, 128>>>(k);
    vq_dist_kernel<<<dim3(NT / 128, 2), 256>>>();
    vq_select_kernel<<<NT / 8, 256>>>(k, out + O_XL);
    // permutation machinery (counting-sort rank, exact stable order)
    vq_bucket_kernel<<<dim3(NT / 256, 2), 256>>>();
    vq_prefix_kernel<<<2, 256>>>();
    vq_rank_kernel<<<NT / 256, 256>>>(0);
    vq_rank_kernel<<<NT / 256, 256>>>(1);
    // outputs
    vq_xd_kernel<<<dim3(TB / 32, WDIM / 32, NB), dim3(32, 32)>>>(k, out + O_XD);
    vq_knew_kernel<<<KC, 128>>>(k, ksum, kelem,
                                out + O_KNEW, out + O_KSUM, out + O_KELEM);
    vq_final_kernel<<<1, 256>>>(out + O_SCAL);
}